// round 4
// baseline (speedup 1.0000x reference)
#include <cuda_runtime.h>

// Problem dims
#define B_   4
#define N_   512
#define D_   512
#define H_   16
#define DH_  32
#define P_   64
#define FINAL_ELEMS (B_ * N_ * D_)      // 1048576 floats, then attn [B,H,N,N]
#define RSQRT_DH 0.17677669529663687f   // 1/sqrt(32)

// Scratch (no cudaMalloc allowed)
__device__ float g_q[B_ * H_ * N_ * DH_];   // [B,H,N,DH]
__device__ float g_k[B_ * H_ * N_ * DH_];
__device__ float g_v[B_ * H_ * N_ * DH_];
__device__ float g_o[B_ * N_ * D_];         // [B,N,D] context before Wo

// Packed fp32x2 FMA (FFMA2) — doubles fp32 FMA throughput on sm_103a.
__device__ __forceinline__ float2 ffma2(float2 a, float2 b, float2 c) {
    float2 d;
    asm("fma.rn.f32x2 %0, %1, %2, %3;"
        : "=l"(reinterpret_cast<unsigned long long &>(d))
        : "l"(reinterpret_cast<unsigned long long &>(a)),
          "l"(reinterpret_cast<unsigned long long &>(b)),
          "l"(reinterpret_cast<unsigned long long &>(c)));
    return d;
}

// ---------------------------------------------------------------------------
// K1: QKV projection. C[2048, 1536] = x[2048,512] @ [Wq|Wk|Wv], scattered into
// g_q/g_k/g_v with [B,H,N,DH] layout. 64x64 tile, BK=16, 256 thr, 4x4 micro.
// ---------------------------------------------------------------------------
__global__ __launch_bounds__(256) void qkv_kernel(
    const float* __restrict__ x, const float* __restrict__ Wq,
    const float* __restrict__ Wk, const float* __restrict__ Wv) {
    __shared__ __align__(16) float As[16][64];
    __shared__ __align__(16) float Bs[16][64];
    int tid = threadIdx.x;
    int tx = tid & 15, ty = tid >> 4;
    int row0 = blockIdx.y << 6;
    int col0 = blockIdx.x << 6;
    int mat = col0 >> 9;
    int wcol0 = col0 & 511;
    const float* W = (mat == 0) ? Wq : ((mat == 1) ? Wk : Wv);

    float2 acc[4][2];
#pragma unroll
    for (int i = 0; i < 4; i++) { acc[i][0] = make_float2(0.f, 0.f); acc[i][1] = make_float2(0.f, 0.f); }

    int arow = tid >> 2, akq = (tid & 3) << 2;
    int brow = tid >> 4, bcol = (tid & 15) << 2;

    for (int kk = 0; kk < 512; kk += 16) {
        float4 av = *(const float4*)(x + (size_t)(row0 + arow) * 512 + kk + akq);
        As[akq + 0][arow] = av.x;
        As[akq + 1][arow] = av.y;
        As[akq + 2][arow] = av.z;
        As[akq + 3][arow] = av.w;
        *(float4*)&Bs[brow][bcol] =
            *(const float4*)(W + (size_t)(kk + brow) * 512 + wcol0 + bcol);
        __syncthreads();
#pragma unroll
        for (int k2 = 0; k2 < 16; k2++) {
            float4 a = *(float4*)&As[k2][ty << 2];
            float4 b = *(float4*)&Bs[k2][tx << 2];
            float2 b01 = make_float2(b.x, b.y);
            float2 b23 = make_float2(b.z, b.w);
            acc[0][0] = ffma2(make_float2(a.x, a.x), b01, acc[0][0]);
            acc[0][1] = ffma2(make_float2(a.x, a.x), b23, acc[0][1]);
            acc[1][0] = ffma2(make_float2(a.y, a.y), b01, acc[1][0]);
            acc[1][1] = ffma2(make_float2(a.y, a.y), b23, acc[1][1]);
            acc[2][0] = ffma2(make_float2(a.z, a.z), b01, acc[2][0]);
            acc[2][1] = ffma2(make_float2(a.z, a.z), b23, acc[2][1]);
            acc[3][0] = ffma2(make_float2(a.w, a.w), b01, acc[3][0]);
            acc[3][1] = ffma2(make_float2(a.w, a.w), b23, acc[3][1]);
        }
        __syncthreads();
    }

    float* dst = (mat == 0) ? g_q : ((mat == 1) ? g_k : g_v);
    int c = wcol0 + (tx << 2);
    int h = c >> 5, dh = c & 31;
#pragma unroll
    for (int i = 0; i < 4; i++) {
        int r = row0 + (ty << 2) + i;
        int bb = r >> 9, n = r & 511;
        float4 v = make_float4(acc[i][0].x, acc[i][0].y, acc[i][1].x, acc[i][1].y);
        *(float4*)&dst[(((size_t)(bb * H_) + h) * N_ + n) * DH_ + dh] = v;
    }
}

// ---------------------------------------------------------------------------
// K2: bias[b,h,n,m] = pair_mask ? sum_p pair_bias[b,n,m,p]*Wp[p,h] : 0
// written into d_out attn region. Skips the pair_bias read when masked (~75%).
// One block per (b,n); 256 threads, 2 m's each.
// ---------------------------------------------------------------------------
__global__ __launch_bounds__(256) void bias_kernel(
    const float* __restrict__ pb, const float* __restrict__ Wp,
    const int* __restrict__ mask, float* __restrict__ attn) {
    __shared__ __align__(16) float Wps[P_ * H_];   // [p][h]
    int tid = threadIdx.x;
    Wps[tid] = Wp[tid];
    Wps[tid + 256] = Wp[tid + 256];
    Wps[tid + 512] = Wp[tid + 512];
    Wps[tid + 768] = Wp[tid + 768];
    __syncthreads();

    int bn = blockIdx.x;
    int bb = bn >> 9, n = bn & 511;
    int mn = mask[bn];

#pragma unroll
    for (int mi = 0; mi < 2; mi++) {
        int m = tid + (mi << 8);
        float2 acc[8];
#pragma unroll
        for (int i = 0; i < 8; i++) acc[i] = make_float2(0.f, 0.f);
        if (mn && mask[(bb << 9) + m]) {
            const float4* pbv = (const float4*)(pb + (((size_t)bn) * N_ + m) * P_);
#pragma unroll
            for (int p4 = 0; p4 < 16; p4++) {
                float4 v = pbv[p4];
                const float2* w = (const float2*)&Wps[(p4 * 4) * H_];
#pragma unroll
                for (int h2 = 0; h2 < 8; h2++) acc[h2] = ffma2(make_float2(v.x, v.x), w[h2],      acc[h2]);
#pragma unroll
                for (int h2 = 0; h2 < 8; h2++) acc[h2] = ffma2(make_float2(v.y, v.y), w[8 + h2],  acc[h2]);
#pragma unroll
                for (int h2 = 0; h2 < 8; h2++) acc[h2] = ffma2(make_float2(v.z, v.z), w[16 + h2], acc[h2]);
#pragma unroll
                for (int h2 = 0; h2 < 8; h2++) acc[h2] = ffma2(make_float2(v.w, v.w), w[24 + h2], acc[h2]);
            }
        }
        size_t base = (((size_t)bb * H_) * N_ + n) * N_ + m;
#pragma unroll
        for (int h = 0; h < H_; h++) {
            float val = (h & 1) ? acc[h >> 1].y : acc[h >> 1].x;
            attn[base + (size_t)h * (N_ * N_)] = val;
        }
    }
}

// ---------------------------------------------------------------------------
// K3: fused attention per (b,h, 16-row tile): scores = qK^T/sqrt(DH) + bias,
// key mask, softmax -> attn (d_out), then attn @ V -> g_o.
// K and V heads resident in smem (stride 36 -> conflict-free, float4-aligned).
// 256 threads = 16 rows x 16 col-groups; thread owns m = j*16+cg, j=0..31.
// ---------------------------------------------------------------------------
#define K3_SMEM_FLOATS (512 * 36 * 2 + 512 + 512)
#define K3_SMEM_BYTES  (K3_SMEM_FLOATS * 4)

__global__ __launch_bounds__(256, 1) void attn_kernel(
    const int* __restrict__ mask, float* __restrict__ attn) {
    extern __shared__ __align__(16) float sm[];
    float* Ks  = sm;                  // [512][36]
    float* Vs  = Ks + 512 * 36;       // [512][36]
    float* qs  = Vs + 512 * 36;       // [16][32]
    float* mok = qs + 512;            // [512]

    int tid = threadIdx.x;
    int bh = blockIdx.y;              // b*H + h
    int bb = bh >> 4;
    int n0 = blockIdx.x << 4;

    const float* gk = g_k + (size_t)bh * (N_ * DH_);
    const float* gv = g_v + (size_t)bh * (N_ * DH_);
    const float* gq = g_q + (size_t)bh * (N_ * DH_);

#pragma unroll
    for (int j = 0; j < 16; j++) {
        int i4 = tid + (j << 8);                // 0..4095 float4s
        int m = i4 >> 3, kq = (i4 & 7) << 2;
        *(float4*)&Ks[m * 36 + kq] = *(const float4*)(gk + ((size_t)i4 << 2));
        *(float4*)&Vs[m * 36 + kq] = *(const float4*)(gv + ((size_t)i4 << 2));
    }
    if (tid < 128)
        *(float4*)&qs[tid << 2] = *(const float4*)(gq + (size_t)n0 * DH_ + (tid << 2));
    mok[tid]       = mask[(bb << 9) + tid]       ? 1.f : 0.f;
    mok[tid + 256] = mask[(bb << 9) + tid + 256] ? 1.f : 0.f;
    __syncthreads();

    int row = tid >> 4, cg = tid & 15;
    int n = n0 + row;

    float2 q2[16];
#pragma unroll
    for (int t = 0; t < 16; t++) q2[t] = *(float2*)&qs[(row << 5) + (t << 1)];

    // scores
    float2 acc2[32];
#pragma unroll
    for (int j = 0; j < 32; j++) acc2[j] = make_float2(0.f, 0.f);
#pragma unroll
    for (int kq = 0; kq < 32; kq += 4) {
        float2 qa = q2[kq >> 1], qb = q2[(kq >> 1) + 1];
#pragma unroll
        for (int j = 0; j < 32; j++) {
            int m = (j << 4) + cg;
            float4 kv = *(float4*)&Ks[m * 36 + kq];
            acc2[j] = ffma2(qa, make_float2(kv.x, kv.y), acc2[j]);
            acc2[j] = ffma2(qb, make_float2(kv.z, kv.w), acc2[j]);
        }
    }

    size_t abase = ((size_t)bh * N_ + n) * N_;
    float s[32];
#pragma unroll
    for (int j = 0; j < 32; j++) {
        int m = (j << 4) + cg;
        float sc = (acc2[j].x + acc2[j].y) * RSQRT_DH + attn[abase + m];
        s[j] = (mok[m] != 0.f) ? sc : -1e6f;
    }

    // softmax over the 512-wide row (32 per thread x 16 lanes in half-warp)
    float mx = -3.0e38f;
#pragma unroll
    for (int j = 0; j < 32; j++) mx = fmaxf(mx, s[j]);
#pragma unroll
    for (int o = 8; o > 0; o >>= 1) mx = fmaxf(mx, __shfl_xor_sync(0xffffffffu, mx, o));
    float sum = 0.f;
#pragma unroll
    for (int j = 0; j < 32; j++) { s[j] = __expf(s[j] - mx); sum += s[j]; }
#pragma unroll
    for (int o = 8; o > 0; o >>= 1) sum += __shfl_xor_sync(0xffffffffu, sum, o);
    float inv = 1.0f / sum;
#pragma unroll
    for (int j = 0; j < 32; j++) s[j] *= inv;
#pragma unroll
    for (int j = 0; j < 32; j++) attn[abase + (j << 4) + cg] = s[j];

    // attn @ V  (partial over this thread's 32 m's, then half-warp reduce)
    float2 pacc[16];
#pragma unroll
    for (int t = 0; t < 16; t++) pacc[t] = make_float2(0.f, 0.f);
#pragma unroll
    for (int j = 0; j < 32; j++) {
        int m = (j << 4) + cg;
        float2 aj = make_float2(s[j], s[j]);
#pragma unroll
        for (int d4 = 0; d4 < 32; d4 += 4) {
            float4 vv = *(float4*)&Vs[m * 36 + d4];
            pacc[d4 >> 1]       = ffma2(aj, make_float2(vv.x, vv.y), pacc[d4 >> 1]);
            pacc[(d4 >> 1) + 1] = ffma2(aj, make_float2(vv.z, vv.w), pacc[(d4 >> 1) + 1]);
        }
    }
#pragma unroll
    for (int o = 8; o > 0; o >>= 1) {
#pragma unroll
        for (int t = 0; t < 16; t++) {
            pacc[t].x += __shfl_xor_sync(0xffffffffu, pacc[t].x, o);
            pacc[t].y += __shfl_xor_sync(0xffffffffu, pacc[t].y, o);
        }
    }
    if (cg == 0) {
        int h = bh & 15;
        float* op = g_o + ((size_t)(bb * N_ + n)) * D_ + (h << 5);
#pragma unroll
        for (int t = 0; t < 16; t++) *(float2*)&op[t << 1] = pacc[t];
    }
}

// ---------------------------------------------------------------------------
// K4: final = (g_o @ Wo), zero masked query rows, write d_out final region.
// ---------------------------------------------------------------------------
__global__ __launch_bounds__(256) void outproj_kernel(
    const float* __restrict__ Wo, const int* __restrict__ mask,
    float* __restrict__ outp) {
    __shared__ __align__(16) float As[16][64];
    __shared__ __align__(16) float Bs[16][64];
    int tid = threadIdx.x;
    int tx = tid & 15, ty = tid >> 4;
    int row0 = blockIdx.y << 6;
    int col0 = blockIdx.x << 6;

    float2 acc[4][2];
#pragma unroll
    for (int i = 0; i < 4; i++) { acc[i][0] = make_float2(0.f, 0.f); acc[i][1] = make_float2(0.f, 0.f); }

    int arow = tid >> 2, akq = (tid & 3) << 2;
    int brow = tid >> 4, bcol = (tid & 15) << 2;

    for (int kk = 0; kk < 512; kk += 16) {
        float4 av = *(const float4*)(g_o + (size_t)(row0 + arow) * 512 + kk + akq);
        As[akq + 0][arow] = av.x;
        As[akq + 1][arow] = av.y;
        As[akq + 2][arow] = av.z;
        As[akq + 3][arow] = av.w;
        *(float4*)&Bs[brow][bcol] =
            *(const float4*)(Wo + (size_t)(kk + brow) * 512 + col0 + bcol);
        __syncthreads();
#pragma unroll
        for (int k2 = 0; k2 < 16; k2++) {
            float4 a = *(float4*)&As[k2][ty << 2];
            float4 b = *(float4*)&Bs[k2][tx << 2];
            float2 b01 = make_float2(b.x, b.y);
            float2 b23 = make_float2(b.z, b.w);
            acc[0][0] = ffma2(make_float2(a.x, a.x), b01, acc[0][0]);
            acc[0][1] = ffma2(make_float2(a.x, a.x), b23, acc[0][1]);
            acc[1][0] = ffma2(make_float2(a.y, a.y), b01, acc[1][0]);
            acc[1][1] = ffma2(make_float2(a.y, a.y), b23, acc[1][1]);
            acc[2][0] = ffma2(make_float2(a.z, a.z), b01, acc[2][0]);
            acc[2][1] = ffma2(make_float2(a.z, a.z), b23, acc[2][1]);
            acc[3][0] = ffma2(make_float2(a.w, a.w), b01, acc[3][0]);
            acc[3][1] = ffma2(make_float2(a.w, a.w), b23, acc[3][1]);
        }
        __syncthreads();
    }

    int c = col0 + (tx << 2);
#pragma unroll
    for (int i = 0; i < 4; i++) {
        int r = row0 + (ty << 2) + i;
        float msk = mask[r] ? 1.f : 0.f;
        float4 v = make_float4(acc[i][0].x * msk, acc[i][0].y * msk,
                               acc[i][1].x * msk, acc[i][1].y * msk);
        *(float4*)&outp[(size_t)r * 512 + c] = v;
    }
}

// ---------------------------------------------------------------------------
extern "C" void kernel_launch(void* const* d_in, const int* in_sizes, int n_in,
                              void* d_out, int out_size) {
    const float* x    = (const float*)d_in[0];
    const float* pb   = (const float*)d_in[1];
    const float* Wq   = (const float*)d_in[2];
    const float* Wk   = (const float*)d_in[3];
    const float* Wv   = (const float*)d_in[4];
    const float* Wo   = (const float*)d_in[5];
    const float* Wp   = (const float*)d_in[6];
    const int*   mask = (const int*)d_in[7];

    float* out  = (float*)d_out;
    float* attn = out + FINAL_ELEMS;

    cudaFuncSetAttribute(attn_kernel, cudaFuncAttributeMaxDynamicSharedMemorySize,
                         K3_SMEM_BYTES);

    qkv_kernel<<<dim3(24, 32), 256>>>(x, Wq, Wk, Wv);
    bias_kernel<<<B_ * N_, 256>>>(pb, Wp, mask, attn);
    attn_kernel<<<dim3(N_ / 16, B_ * H_), 256, K3_SMEM_BYTES>>>(mask, attn);
    outproj_kernel<<<dim3(8, 32), 256>>>(Wo, mask, out);
}